// round 1
// baseline (speedup 1.0000x reference)
#include <cuda_runtime.h>
#include <math.h>

#define Wd 256
#define Hd 256
#define NP (Wd*Hd)
#define NG 1024
#define MF 50
#define NCH 150       // MF*3
#define PADCH 151     // odd pad -> conflict-free smem
#define NTILES 256    // 16x16 tiles of 16x16 px
#define CHUNK 8
#define HITCAP (CHUNK*256)

// ---- scratch (static __device__, no allocation) ----
__device__ float g_cx[NG], g_cy[NG], g_c1[NG], g_c2[NG], g_c3[NG], g_op[NG], g_T[NG];
__device__ float g_featT[NG * NCH];     // [n][m*3+c]
__device__ int   g_tileCount[NTILES];
__device__ int   g_tileList[NTILES * NG];

__global__ void zero_counts_kernel() {
    if (threadIdx.x < NTILES) g_tileCount[threadIdx.x] = 0;
}

__global__ void prep_kernel(const float* __restrict__ xyz,
                            const float* __restrict__ chol,
                            const float* __restrict__ opac) {
    int n = blockIdx.x * blockDim.x + threadIdx.x;
    if (n >= NG) return;
    float l1 = chol[n*3+0] + 0.5f;
    float l2 = chol[n*3+1];
    float l3 = chol[n*3+2] + 0.5f;
    float a = l1*l1, b = l1*l2, c = l2*l2 + l3*l3;
    float det = a*c - b*b;
    float inv = 1.0f / det;
    float c1 = c*inv, c2 = -b*inv, c3 = a*inv;
    float cx = 0.5f*((tanhf(xyz[n*2+0]) + 1.0f)*(float)Wd - 1.0f);
    float cy = 0.5f*((tanhf(xyz[n*2+1]) + 1.0f)*(float)Hd - 1.0f);
    float op = opac[n];
    g_cx[n]=cx; g_cy[n]=cy; g_c1[n]=c1; g_c2[n]=c2; g_c3[n]=c3; g_op[n]=op;
    // valid iff sigma <= T = ln(255*op)  (and sigma>=0)
    float T = (op > 0.f) ? logf(255.0f*op) : -1.0f;
    g_T[n] = T;
    if (T < 0.f) return;
    // conservative bbox of ellipse d^T Sigma^-1 d <= 2T : |dx|<=sqrt(2T*a), |dy|<=sqrt(2T*c)
    float rx = sqrtf(fmaxf(0.f, 2.0f*T*a)) + 1.0f;
    float ry = sqrtf(fmaxf(0.f, 2.0f*T*c)) + 1.0f;
    int x0 = max(0,    (int)floorf(cx - rx));
    int x1 = min(Wd-1, (int)ceilf (cx + rx));
    int y0 = max(0,    (int)floorf(cy - ry));
    int y1 = min(Hd-1, (int)ceilf (cy + ry));
    if (x0 > x1 || y0 > y1) return;
    for (int ty = (y0 >> 4); ty <= (y1 >> 4); ty++)
        for (int tx = (x0 >> 4); tx <= (x1 >> 4); tx++) {
            int t = ty*16 + tx;
            int slot = atomicAdd(&g_tileCount[t], 1);
            g_tileList[t*NG + slot] = n;
        }
}

__global__ void transpose_feat_kernel(const float* __restrict__ feats,
                                      const int* __restrict__ cid_ptr) {
    int idx = blockIdx.x * blockDim.x + threadIdx.x;   // over NG*NCH
    if (idx >= NG*NCH) return;
    int n  = idx / NCH;
    int mc = idx - n*NCH;
    int m  = mc / 3;
    int c  = mc - m*3;
    int cid = cid_ptr[0];
    // features_dc[k][m][n][c] : ((k*MF+m)*NG + n)*3 + c
    g_featT[n*NCH + mc] = feats[(((long)cid*MF + m)*NG + n)*3 + c];
}

__global__ void __launch_bounds__(256, 1)
render_kernel(float* __restrict__ out) {
    extern __shared__ float sm[];
    float*    accS     = sm;                       // 256*PADCH
    float*    hitAlpha = sm + 256*PADCH;           // HITCAP
    unsigned* hitKey   = (unsigned*)(hitAlpha + HITCAP);
    __shared__ int s_cnt;

    int tile = blockIdx.x;
    int tx = tile & 15, ty = tile >> 4;
    int t  = threadIdx.x;                          // 0..255 -> pixel in tile
    int lx = t & 15, ly = t >> 4;
    float px = (float)(tx*16 + lx);
    float py = (float)(ty*16 + ly);

    for (int i = t; i < 256*PADCH; i += 256) accS[i] = 0.f;

    int count = g_tileCount[tile];
    const int* __restrict__ list = &g_tileList[tile*NG];
    int warp = t >> 5, lane = t & 31;

    for (int base = 0; base < count; base += CHUNK) {
        if (t == 0) s_cnt = 0;
        __syncthreads();
        int lim = min(CHUNK, count - base);
        for (int j = 0; j < lim; j++) {
            int n = list[base + j];
            float dx = g_cx[n] - px;
            float dy = g_cy[n] - py;
            float sigma = 0.5f*(g_c1[n]*dx*dx + g_c3[n]*dy*dy) + g_c2[n]*dx*dy;
            if (sigma >= 0.f && sigma <= g_T[n] + 1e-3f) {
                float alpha = fminf(0.999f, g_op[n]*expf(-sigma));
                if (alpha >= (1.0f/255.0f)) {
                    int slot = atomicAdd(&s_cnt, 1);
                    hitKey[slot]   = ((unsigned)n << 8) | (unsigned)t;
                    hitAlpha[slot] = alpha;
                }
            }
        }
        __syncthreads();
        int hc = s_cnt;
        for (int h = warp; h < hc; h += 8) {
            unsigned key = hitKey[h];
            float a = hitAlpha[h];
            int n   = (int)(key >> 8);
            int pix = (int)(key & 255u);
            const float* __restrict__ f = &g_featT[n*NCH];
            for (int mc = lane; mc < NCH; mc += 32)
                atomicAdd(&accS[pix*PADCH + mc], a * f[mc]);
        }
        __syncthreads();
    }

    // write out[mc][y][x]
    int pixBase = (ty*16 + ly)*Wd + tx*16 + lx;
    #pragma unroll 5
    for (int mc = 0; mc < NCH; mc++)
        out[mc*NP + pixBase] = accS[t*PADCH + mc];
}

extern "C" void kernel_launch(void* const* d_in, const int* in_sizes, int n_in,
                              void* d_out, int out_size) {
    const float* xyz   = (const float*)d_in[0];
    const float* chol  = (const float*)d_in[1];
    const float* opac  = (const float*)d_in[2];
    const float* feats = (const float*)d_in[3];
    const int*   cid   = (const int*)  d_in[4];
    float* out = (float*)d_out;

    static int smem_set = 0;
    int smem_bytes = (256*PADCH + HITCAP)*4 + HITCAP*4;
    if (!smem_set) {
        cudaFuncSetAttribute(render_kernel,
                             cudaFuncAttributeMaxDynamicSharedMemorySize, smem_bytes);
        smem_set = 1;
    }

    zero_counts_kernel<<<1, 256>>>();
    prep_kernel<<<4, 256>>>(xyz, chol, opac);
    transpose_feat_kernel<<<(NG*NCH + 255)/256, 256>>>(feats, cid);
    render_kernel<<<NTILES, 256, smem_bytes>>>(out);
}

// round 2
// speedup vs baseline: 2.6564x; 2.6564x over previous
#include <cuda_runtime.h>
#include <math.h>

#define Wd 256
#define Hd 256
#define NP (Wd*Hd)
#define NG 1024
#define MF 50
#define NCH 150        // MF*3
#define NTILES 256     // 16x16 tiles of 16x16 px
#define GROUPS 3
#define GCH 50         // channels per group
#define GCH4 13        // 13 float4 = 52 (2 pad)
#define CCHUNK 32      // candidates staged per chunk

// ---- scratch (static __device__, no allocation) ----
__device__ float g_cx[NG], g_cy[NG], g_c1[NG], g_c2[NG], g_c3[NG], g_op[NG];
__device__ float g_featT[NG * NCH];     // [n][m*3+c]
__device__ int   g_tileCount[NTILES];
__device__ int   g_tileList[NTILES * NG];

__global__ void zero_counts_kernel() {
    if (threadIdx.x < NTILES) g_tileCount[threadIdx.x] = 0;
}

__global__ void prep_kernel(const float* __restrict__ xyz,
                            const float* __restrict__ chol,
                            const float* __restrict__ opac) {
    int n = blockIdx.x * blockDim.x + threadIdx.x;
    if (n >= NG) return;
    float l1 = chol[n*3+0] + 0.5f;
    float l2 = chol[n*3+1];
    float l3 = chol[n*3+2] + 0.5f;
    float a = l1*l1, b = l1*l2, c = l2*l2 + l3*l3;
    float det = a*c - b*b;
    float inv = 1.0f / det;
    float c1 = c*inv, c2 = -b*inv, c3 = a*inv;
    float cx = 0.5f*((tanhf(xyz[n*2+0]) + 1.0f)*(float)Wd - 1.0f);
    float cy = 0.5f*((tanhf(xyz[n*2+1]) + 1.0f)*(float)Hd - 1.0f);
    float op = opac[n];
    g_cx[n]=cx; g_cy[n]=cy; g_c1[n]=c1; g_c2[n]=c2; g_c3[n]=c3; g_op[n]=op;
    // alpha >= 1/255  <=>  sigma <= T = ln(255*op)   (sigma >= 0 always, det = l1^2 l3^2 > 0)
    float T = (op > 0.f) ? logf(255.0f*op) : -1.0f;
    if (T < 0.f) return;
    // conservative bbox: max |dx| over {0.5 d^T conic d <= T} = sqrt(2T*a), |dy| = sqrt(2T*c)
    float rx = sqrtf(fmaxf(0.f, 2.0f*T*a)) + 1.0f;
    float ry = sqrtf(fmaxf(0.f, 2.0f*T*c)) + 1.0f;
    int x0 = max(0,    (int)floorf(cx - rx));
    int x1 = min(Wd-1, (int)ceilf (cx + rx));
    int y0 = max(0,    (int)floorf(cy - ry));
    int y1 = min(Hd-1, (int)ceilf (cy + ry));
    if (x0 > x1 || y0 > y1) return;
    for (int ty = (y0 >> 4); ty <= (y1 >> 4); ty++)
        for (int tx = (x0 >> 4); tx <= (x1 >> 4); tx++) {
            int t = ty*16 + tx;
            int slot = atomicAdd(&g_tileCount[t], 1);
            g_tileList[t*NG + slot] = n;
        }
}

__global__ void transpose_feat_kernel(const float* __restrict__ feats,
                                      const int* __restrict__ cid_ptr) {
    int idx = blockIdx.x * blockDim.x + threadIdx.x;   // over NG*NCH
    if (idx >= NG*NCH) return;
    int n  = idx / NCH;
    int mc = idx - n*NCH;
    int m  = mc / 3;
    int c  = mc - m*3;
    int cid = cid_ptr[0];
    // features_dc[k][m][n][c] : ((k*MF+m)*NG + n)*3 + c
    g_featT[n*NCH + mc] = feats[(((long)cid*MF + m)*NG + n)*3 + c];
}

// One block = (tile, channel-group). Each thread owns one pixel and keeps
// 52 fp32 accumulators in registers. No atomics anywhere.
__global__ void __launch_bounds__(256, 2)
render_kernel(float* __restrict__ out) {
    __shared__ float4 sfeat[CCHUNK][GCH4];                 // 6656 B
    __shared__ float  s_cx[CCHUNK], s_cy[CCHUNK];
    __shared__ float  s_c1[CCHUNK], s_c2[CCHUNK], s_c3[CCHUNK], s_op[CCHUNK];

    int tile = blockIdx.x;
    int grp  = blockIdx.y;
    int tx = tile & 15, ty = tile >> 4;
    int t  = threadIdx.x;                                  // pixel within tile
    int lx = t & 15, ly = t >> 4;
    float px = (float)(tx*16 + lx);
    float py = (float)(ty*16 + ly);

    float acc[GCH4*4];
    #pragma unroll
    for (int i = 0; i < GCH4*4; i++) acc[i] = 0.f;

    int count = g_tileCount[tile];
    const int* __restrict__ list = &g_tileList[tile*NG];
    const int chbase = grp * GCH;

    for (int base = 0; base < count; base += CCHUNK) {
        int lim = min(CCHUNK, count - base);
        // stage gaussian params (threads 0..lim-1)
        if (t < lim) {
            int n = list[base + t];
            s_cx[t] = g_cx[n]; s_cy[t] = g_cy[n];
            s_c1[t] = g_c1[n]; s_c2[t] = g_c2[n]; s_c3[t] = g_c3[n];
            s_op[t] = g_op[n];
        }
        // stage this group's feature rows (52 floats per candidate, 2 zero-pad)
        for (int i = t; i < lim*GCH4*4; i += 256) {
            int j = i / (GCH4*4);
            int c = i - j*(GCH4*4);
            int n = list[base + j];
            float v = (c < GCH) ? g_featT[n*NCH + chbase + c] : 0.f;
            ((float*)sfeat)[j*(GCH4*4) + c] = v;
        }
        __syncthreads();

        for (int j = 0; j < lim; j++) {
            float dx = s_cx[j] - px;
            float dy = s_cy[j] - py;
            float sigma = 0.5f*(s_c1[j]*dx*dx + s_c3[j]*dy*dy) + s_c2[j]*dx*dy;
            float a = 0.f;
            if (sigma >= 0.f && sigma < 8.f) {             // alpha < e^-8 < 1/255 guaranteed miss
                float al = fminf(0.999f, s_op[j]*__expf(-sigma));
                if (al >= (1.0f/255.0f)) a = al;
            }
            if (__ballot_sync(0xffffffffu, a != 0.f)) {
                #pragma unroll
                for (int q = 0; q < GCH4; q++) {
                    float4 f = sfeat[j][q];
                    acc[4*q+0] = fmaf(a, f.x, acc[4*q+0]);
                    acc[4*q+1] = fmaf(a, f.y, acc[4*q+1]);
                    acc[4*q+2] = fmaf(a, f.z, acc[4*q+2]);
                    acc[4*q+3] = fmaf(a, f.w, acc[4*q+3]);
                }
            }
        }
        __syncthreads();
    }

    // out[mc][y][x], this block's channels are [chbase, chbase+GCH)
    int pixBase = (ty*16 + ly)*Wd + tx*16 + lx;
    float* o = out + (long)chbase*NP + pixBase;
    #pragma unroll
    for (int c = 0; c < GCH; c++)
        o[(long)c*NP] = acc[c];
}

extern "C" void kernel_launch(void* const* d_in, const int* in_sizes, int n_in,
                              void* d_out, int out_size) {
    const float* xyz   = (const float*)d_in[0];
    const float* chol  = (const float*)d_in[1];
    const float* opac  = (const float*)d_in[2];
    const float* feats = (const float*)d_in[3];
    const int*   cid   = (const int*)  d_in[4];
    float* out = (float*)d_out;

    zero_counts_kernel<<<1, 256>>>();
    prep_kernel<<<4, 256>>>(xyz, chol, opac);
    transpose_feat_kernel<<<(NG*NCH + 255)/256, 256>>>(feats, cid);
    dim3 grid(NTILES, GROUPS);
    render_kernel<<<grid, 256>>>(out);
}

// round 4
// speedup vs baseline: 3.1182x; 1.1739x over previous
#include <cuda_runtime.h>
#include <math.h>

#define Wd 256
#define Hd 256
#define NP (Wd*Hd)
#define NG 1024
#define MF 50
#define NCH 150        // MF*3
#define NTILES 256     // 16x16 tiles of 16x16 px
#define GROUPS 6
#define GCH 25         // channels per group
#define GCH4 7         // 7 float4 = 28 (3 pad)
#define GPAD (GCH4*4)  // 28
#define CCHUNK 32      // candidates staged per chunk

// ---- scratch (static __device__, no allocation) ----
__device__ float g_cx[NG], g_cy[NG], g_c1[NG], g_c2[NG], g_c3[NG], g_op[NG];
__device__ int   g_tileCount[NTILES];
__device__ int   g_tileList[NTILES * NG];

// Single block, 1024 threads: zero counters in smem, bin all gaussians, flush.
__global__ void __launch_bounds__(1024, 1)
prep_kernel(const float* __restrict__ xyz,
            const float* __restrict__ chol,
            const float* __restrict__ opac) {
    __shared__ int s_cnt[NTILES];
    int n = threadIdx.x;
    if (n < NTILES) s_cnt[n] = 0;
    __syncthreads();

    float l1 = chol[n*3+0] + 0.5f;
    float l2 = chol[n*3+1];
    float l3 = chol[n*3+2] + 0.5f;
    float a = l1*l1, b = l1*l2, c = l2*l2 + l3*l3;
    float det = a*c - b*b;
    float inv = 1.0f / det;
    float cx = 0.5f*((tanhf(xyz[n*2+0]) + 1.0f)*(float)Wd - 1.0f);
    float cy = 0.5f*((tanhf(xyz[n*2+1]) + 1.0f)*(float)Hd - 1.0f);
    float op = opac[n];
    g_cx[n]=cx; g_cy[n]=cy;
    g_c1[n]=c*inv; g_c2[n]=-b*inv; g_c3[n]=a*inv; g_op[n]=op;

    // alpha >= 1/255  <=>  sigma <= T = ln(255*op); sigma >= 0 always (det>0)
    float T = (op > 0.f) ? logf(255.0f*op) : -1.0f;
    if (T >= 0.f) {
        // conservative bbox: max |dx| on {0.5 d^T conic d = T} is sqrt(2T*Sigma_xx)
        float rx = sqrtf(fmaxf(0.f, 2.0f*T*a)) + 1.0f;
        float ry = sqrtf(fmaxf(0.f, 2.0f*T*c)) + 1.0f;
        int x0 = max(0,    (int)floorf(cx - rx));
        int x1 = min(Wd-1, (int)ceilf (cx + rx));
        int y0 = max(0,    (int)floorf(cy - ry));
        int y1 = min(Hd-1, (int)ceilf (cy + ry));
        if (x0 <= x1 && y0 <= y1) {
            for (int ty = (y0 >> 4); ty <= (y1 >> 4); ty++)
                for (int tx = (x0 >> 4); tx <= (x1 >> 4); tx++) {
                    int t = ty*16 + tx;
                    int slot = atomicAdd(&s_cnt[t], 1);
                    g_tileList[t*NG + slot] = n;
                }
        }
    }
    __syncthreads();
    if (n < NTILES) g_tileCount[n] = s_cnt[n];
}

// One block = (tile, channel-group of 25). Each thread owns one pixel,
// 28 fp32 register accumulators. Features read directly from input (L2-hot).
__global__ void __launch_bounds__(256, 4)
render_kernel(float* __restrict__ out,
              const float* __restrict__ feats,
              const int* __restrict__ cid_ptr) {
    __shared__ float4 sfeat[CCHUNK][GCH4];                 // 3584 B
    __shared__ float  s_cx[CCHUNK], s_cy[CCHUNK];
    __shared__ float  s_c1[CCHUNK], s_c2[CCHUNK], s_c3[CCHUNK], s_op[CCHUNK];

    int tile = blockIdx.x;
    int grp  = blockIdx.y;
    int tx = tile & 15, ty = tile >> 4;
    int t  = threadIdx.x;                                  // pixel within tile
    float px = (float)(tx*16 + (t & 15));
    float py = (float)(ty*16 + (t >> 4));

    float acc[GPAD];
    #pragma unroll
    for (int i = 0; i < GPAD; i++) acc[i] = 0.f;

    int count = g_tileCount[tile];
    const int* __restrict__ list = &g_tileList[tile*NG];
    const int chbase = grp * GCH;
    const float* __restrict__ fbase = feats + (long)cid_ptr[0]*MF*NG*3;

    for (int base = 0; base < count; base += CCHUNK) {
        int lim = min(CCHUNK, count - base);
        if (t < lim) {
            int n = list[base + t];
            s_cx[t] = g_cx[n]; s_cy[t] = g_cy[n];
            s_c1[t] = g_c1[n]; s_c2[t] = g_c2[n]; s_c3[t] = g_c3[n];
            s_op[t] = g_op[n];
        }
        // stage features: candidate j, padded channel c -> feats[(m*NG+n)*3+cc]
        for (int i = t; i < lim*GPAD; i += 256) {
            int j = i / GPAD;
            int c = i - j*GPAD;
            float v = 0.f;
            if (c < GCH) {
                int ch = chbase + c;
                int m  = ch / 3;
                int cc = ch - m*3;
                int n  = list[base + j];
                v = fbase[(m*NG + n)*3 + cc];
            }
            ((float*)sfeat)[i] = v;
        }
        __syncthreads();

        for (int j = 0; j < lim; j++) {
            float dx = s_cx[j] - px;
            float dy = s_cy[j] - py;
            float sigma = 0.5f*(s_c1[j]*dx*dx + s_c3[j]*dy*dy) + s_c2[j]*dx*dy;
            float a = 0.f;
            if (sigma >= 0.f && sigma < 8.f) {             // e^-8 < 1/255: guaranteed miss
                float al = fminf(0.999f, s_op[j]*__expf(-sigma));
                if (al >= (1.0f/255.0f)) a = al;
            }
            if (__ballot_sync(0xffffffffu, a != 0.f)) {
                #pragma unroll
                for (int q = 0; q < GCH4; q++) {
                    float4 f = sfeat[j][q];
                    acc[4*q+0] = fmaf(a, f.x, acc[4*q+0]);
                    acc[4*q+1] = fmaf(a, f.y, acc[4*q+1]);
                    acc[4*q+2] = fmaf(a, f.z, acc[4*q+2]);
                    acc[4*q+3] = fmaf(a, f.w, acc[4*q+3]);
                }
            }
        }
        __syncthreads();
    }

    // out[mc][y][x]; this block's channels are [chbase, chbase+GCH)
    int pixBase = (ty*16 + (t >> 4))*Wd + tx*16 + (t & 15);
    float* o = out + chbase*NP + pixBase;
    #pragma unroll
    for (int c = 0; c < GCH; c++)
        o[c*NP] = acc[c];
}

extern "C" void kernel_launch(void* const* d_in, const int* in_sizes, int n_in,
                              void* d_out, int out_size) {
    const float* xyz   = (const float*)d_in[0];
    const float* chol  = (const float*)d_in[1];
    const float* opac  = (const float*)d_in[2];
    const float* feats = (const float*)d_in[3];
    const int*   cid   = (const int*)  d_in[4];
    float* out = (float*)d_out;

    prep_kernel<<<1, 1024>>>(xyz, chol, opac);
    dim3 grid(NTILES, GROUPS);
    render_kernel<<<grid, 256>>>(out, feats, cid);
}

// round 5
// speedup vs baseline: 3.3613x; 1.0780x over previous
#include <cuda_runtime.h>
#include <math.h>

#define Wd 256
#define Hd 256
#define NP (Wd*Hd)
#define NG 1024
#define MF 50
#define NCH 150
#define NTILES 256     // 16x16 tiles of 16x16 px
#define GROUPS 6
#define GCH 25         // channels per group
#define NQ 8           // float4 quads per (n,grp): 32 floats (25 used, 7 zero-pad)
#define CCHUNK 32
#define NITEMS (NTILES*GROUPS)
#define NBLOCKS 608    // 152 SM * 4 resident CTAs (work-stealing: extras are harmless)

// ---- scratch (static __device__, no allocation) ----
__device__ float4 g_p0[NG];                 // cx, cy, h1=0.5*conic1, c2=conic2
__device__ float4 g_p1[NG];                 // h3=0.5*conic3, op, 0, 0
__device__ float4 g_featTP[NG*GROUPS*NQ];   // [n][grp][q] padded transpose
__device__ int    g_tileCount[NTILES];
__device__ int    g_tileList[NTILES*NG];
__device__ int    g_work;

__device__ __forceinline__ void fma2(unsigned long long& acc,
                                     unsigned long long a2,
                                     unsigned long long f2) {
    asm("fma.rn.f32x2 %0, %1, %2, %0;" : "+l"(acc) : "l"(a2), "l"(f2));
}

// Block 0: bin gaussians + write packed params (1024 threads, 1 gaussian each).
// Blocks 1..48: transpose features into padded [n][grp][32] layout.
__global__ void __launch_bounds__(1024, 1)
prep_kernel(const float* __restrict__ xyz,
            const float* __restrict__ chol,
            const float* __restrict__ opac,
            const float* __restrict__ feats,
            const int* __restrict__ cid_ptr) {
    const float* __restrict__ fbase = feats + (long)cid_ptr[0]*MF*NG*3;

    if (blockIdx.x != 0) {
        // transpose: element e over NG*GROUPS*32 floats
        int e0 = (blockIdx.x - 1) * 4096 + threadIdx.x;
        #pragma unroll
        for (int k = 0; k < 4; k++) {
            int e = e0 + k*1024;                 // < 1024*192
            int n = e / 192;
            int r = e - n*192;                   // grp*32 + c
            int grp = r >> 5;
            int c   = r & 31;
            float v = 0.f;
            if (c < GCH) {
                int ch = grp*GCH + c;
                int m  = ch / 3;
                int cc = ch - m*3;
                v = fbase[(m*NG + n)*3 + cc];
            }
            ((float*)g_featTP)[e] = v;
        }
        return;
    }

    __shared__ int s_cnt[NTILES];
    int n = threadIdx.x;
    if (n < NTILES) s_cnt[n] = 0;
    if (n == 0) g_work = 0;
    __syncthreads();

    float l1 = chol[n*3+0] + 0.5f;
    float l2 = chol[n*3+1];
    float l3 = chol[n*3+2] + 0.5f;
    float a = l1*l1, b = l1*l2, c = l2*l2 + l3*l3;
    float det = a*c - b*b;
    float inv = 1.0f / det;
    float cx = 0.5f*((tanhf(xyz[n*2+0]) + 1.0f)*(float)Wd - 1.0f);
    float cy = 0.5f*((tanhf(xyz[n*2+1]) + 1.0f)*(float)Hd - 1.0f);
    float op = opac[n];
    g_p0[n] = make_float4(cx, cy, 0.5f*c*inv, -b*inv);
    g_p1[n] = make_float4(0.5f*a*inv, op, 0.f, 0.f);

    // alpha >= 1/255 <=> sigma <= T = ln(255*op); sigma >= 0 always (det > 0)
    float T = (op > 0.f) ? logf(255.0f*op) : -1.0f;
    if (T >= 0.f) {
        float rx = sqrtf(fmaxf(0.f, 2.0f*T*a)) + 1.0f;  // bbox: sqrt(2T*Sigma_xx)
        float ry = sqrtf(fmaxf(0.f, 2.0f*T*c)) + 1.0f;
        int x0 = max(0,    (int)floorf(cx - rx));
        int x1 = min(Wd-1, (int)ceilf (cx + rx));
        int y0 = max(0,    (int)floorf(cy - ry));
        int y1 = min(Hd-1, (int)ceilf (cy + ry));
        if (x0 <= x1 && y0 <= y1) {
            for (int ty = (y0 >> 4); ty <= (y1 >> 4); ty++)
                for (int tx = (x0 >> 4); tx <= (x1 >> 4); tx++) {
                    int t = ty*16 + tx;
                    int slot = atomicAdd(&s_cnt[t], 1);
                    g_tileList[t*NG + slot] = n;
                }
        }
    }
    __syncthreads();
    if (n < NTILES) g_tileCount[n] = s_cnt[n];
}

// Persistent blocks; each steals (tile, channel-group) items. One thread = one
// pixel, 28 fp32 register accumulators updated via packed fma.rn.f32x2.
__global__ void __launch_bounds__(256, 4)
render_kernel(float* __restrict__ out) {
    __shared__ float4 s_p0[CCHUNK], s_p1[CCHUNK];
    __shared__ float4 sfeat[CCHUNK][NQ];         // 4 KB
    __shared__ int s_item;

    int t = threadIdx.x;

    for (;;) {
        __syncthreads();                          // protect s_item reuse
        if (t == 0) s_item = atomicAdd(&g_work, 1);
        __syncthreads();
        int item = s_item;
        if (item >= NITEMS) return;

        int tile = item & 255;
        int grp  = item >> 8;
        int tx = tile & 15, ty = tile >> 4;
        float px = (float)(tx*16 + (t & 15));
        float py = (float)(ty*16 + (t >> 4));

        unsigned long long acc2[14];
        #pragma unroll
        for (int k = 0; k < 14; k++) acc2[k] = 0ull;

        int count = g_tileCount[tile];
        const int* __restrict__ list = &g_tileList[tile*NG];
        const float4* __restrict__ fTP = g_featTP + grp*NQ;

        for (int base = 0; base < count; base += CCHUNK) {
            int lim = min(CCHUNK, count - base);
            if (t < lim) {
                int n = list[base + t];
                s_p0[t] = g_p0[n];
                s_p1[t] = g_p1[n];
            }
            for (int i = t; i < lim*NQ; i += 256) {
                int j = i >> 3, q = i & 7;
                int n = list[base + j];
                sfeat[j][q] = fTP[n*(GROUPS*NQ) + q];
            }
            __syncthreads();

            for (int j = 0; j < lim; j++) {
                float4 p0 = s_p0[j];
                float4 p1 = s_p1[j];
                float dx = p0.x - px;
                float dy = p0.y - py;
                float sigma = p0.z*dx*dx + p1.x*dy*dy + p0.w*dx*dy;
                float a = 0.f;
                if (sigma >= 0.f) {
                    float al = fminf(0.999f, p1.y*__expf(-sigma));
                    if (al >= (1.0f/255.0f)) a = al;
                }
                if (__any_sync(0xffffffffu, a != 0.f)) {
                    unsigned long long a2;
                    asm("mov.b64 %0, {%1, %1};" : "=l"(a2) : "f"(a));
                    const ulonglong2* __restrict__ sf =
                        (const ulonglong2*)&sfeat[j][0];
                    #pragma unroll
                    for (int q = 0; q < 7; q++) {
                        ulonglong2 u = sf[q];                 // LDS.128 broadcast
                        fma2(acc2[2*q],   a2, u.x);
                        fma2(acc2[2*q+1], a2, u.y);
                    }
                }
            }
            __syncthreads();
        }

        // out[mc][y][x]; channels [grp*25, grp*25+25)
        float accf[28];
        #pragma unroll
        for (int k = 0; k < 14; k++)
            asm("mov.b64 {%0, %1}, %2;"
                : "=f"(accf[2*k]), "=f"(accf[2*k+1]) : "l"(acc2[k]));
        int pixBase = (ty*16 + (t >> 4))*Wd + tx*16 + (t & 15);
        float* o = out + grp*GCH*NP + pixBase;
        #pragma unroll
        for (int c = 0; c < GCH; c++)
            o[c*NP] = accf[c];
    }
}

extern "C" void kernel_launch(void* const* d_in, const int* in_sizes, int n_in,
                              void* d_out, int out_size) {
    const float* xyz   = (const float*)d_in[0];
    const float* chol  = (const float*)d_in[1];
    const float* opac  = (const float*)d_in[2];
    const float* feats = (const float*)d_in[3];
    const int*   cid   = (const int*)  d_in[4];
    float* out = (float*)d_out;

    prep_kernel<<<49, 1024>>>(xyz, chol, opac, feats, cid);
    render_kernel<<<NBLOCKS, 256>>>(out);
}